// round 3
// baseline (speedup 1.0000x reference)
#include <cuda_runtime.h>
#include <cuda_bf16.h>

// Problem constants (fixed by the reference)
#define NN 100000
#define NE 1600000
#define FIN 128
#define FH  128
#define FC  40

// ---------------- device scratch (no allocs allowed) ----------------
__device__ int   g_deg_out[NN];
__device__ int   g_deg_in[NN];
__device__ int   g_fill[NN];
__device__ int   g_row_off[NN + 1];
__device__ int   g_csr_src[NE];
__device__ float g_src_norm[NN];
__device__ float g_dst_norm[NN];
__device__ float g_xw [(size_t)NN * FH];   // (x*src_norm) @ W1
__device__ float g_hs2[(size_t)NN * FH];   // relu(agg*dn + b1) * src_norm
__device__ float g_hw [(size_t)NN * FC];   // hs2 @ W2

// ---------------- setup kernels ----------------
__global__ __launch_bounds__(256) void k_zero() {
    int i = blockIdx.x * blockDim.x + threadIdx.x;
    if (i < NN) { g_deg_out[i] = 0; g_deg_in[i] = 0; g_fill[i] = 0; }
}

__global__ __launch_bounds__(256) void k_hist(const int* __restrict__ src,
                                              const int* __restrict__ dst) {
    int e = blockIdx.x * blockDim.x + threadIdx.x;
    if (e < NE) {
        atomicAdd(&g_deg_out[src[e]], 1);
        atomicAdd(&g_deg_in [dst[e]], 1);
    }
}

// single-block exclusive scan of g_deg_in -> g_row_off (N=100000)
__global__ __launch_bounds__(1024) void k_scan() {
    __shared__ int ssum[1024];
    const int CH = (NN + 1023) / 1024;   // 98
    int tid = threadIdx.x;
    int base = tid * CH;
    int s = 0;
    for (int i = 0; i < CH; i++) {
        int idx = base + i;
        if (idx < NN) s += g_deg_in[idx];
    }
    ssum[tid] = s;
    __syncthreads();
    // Hillis-Steele inclusive scan
    for (int d = 1; d < 1024; d <<= 1) {
        int v = (tid >= d) ? ssum[tid - d] : 0;
        __syncthreads();
        ssum[tid] += v;
        __syncthreads();
    }
    int run = (tid == 0) ? 0 : ssum[tid - 1];
    for (int i = 0; i < CH; i++) {
        int idx = base + i;
        if (idx < NN) { g_row_off[idx] = run; run += g_deg_in[idx]; }
    }
    if (tid == 1023) g_row_off[NN] = ssum[1023];
}

__global__ __launch_bounds__(256) void k_norm() {
    int i = blockIdx.x * blockDim.x + threadIdx.x;
    if (i < NN) {
        g_src_norm[i] = rsqrtf((float)max(g_deg_out[i], 1));
        g_dst_norm[i] = rsqrtf((float)max(g_deg_in [i], 1));
    }
}

__global__ __launch_bounds__(256) void k_fill(const int* __restrict__ src,
                                              const int* __restrict__ dst) {
    int e = blockIdx.x * blockDim.x + threadIdx.x;
    if (e < NE) {
        int d = dst[e];
        int p = g_row_off[d] + atomicAdd(&g_fill[d], 1);
        g_csr_src[p] = src[e];
    }
}

// ---------------- dense GEMM: Y[M,NC] = diag(rowscale) * X[M,128] @ W[128,NC]
// K-tiled (KT=32) so static smem stays < 48KB. 256 threads, 64 rows/block.
// Thread computes RPT rows x CPT cols in registers.
template<int NC, int TX, int CPT, int RPT>
__global__ __launch_bounds__(256) void k_gemm(const float* __restrict__ X,
                                              const float* __restrict__ W,
                                              const float* __restrict__ rowscale,
                                              float* __restrict__ Y) {
    static_assert(TX * CPT == NC, "cols");
    static_assert((256 / TX) * RPT == 64, "rows");
    const int BM = 64, KT = 32;
    __shared__ float sW[KT][NC];       // 32*NC floats
    __shared__ float sX[BM][KT + 1];   // 64*33 floats (pad kills conflicts)

    int tid  = threadIdx.x;
    int row0 = blockIdx.x * BM;
    int tx = tid % TX, ty = tid / TX;

    float acc[RPT][CPT];
#pragma unroll
    for (int i = 0; i < RPT; i++)
#pragma unroll
        for (int j = 0; j < CPT; j++) acc[i][j] = 0.f;

    const bool has_rs = (rowscale != nullptr);

    for (int kt = 0; kt < 128; kt += KT) {
        for (int i = tid; i < KT * NC; i += 256)
            sW[i / NC][i % NC] = W[(size_t)(kt + i / NC) * NC + (i % NC)];
        for (int i = tid; i < BM * KT; i += 256) {
            int r = i >> 5, c = i & 31;
            int gr = row0 + r;
            float v = 0.f;
            if (gr < NN) {
                v = X[(size_t)gr * 128 + kt + c];
                if (has_rs) v *= rowscale[gr];
            }
            sX[r][c] = v;
        }
        __syncthreads();

#pragma unroll
        for (int k = 0; k < KT; k++) {
            float wv[CPT];
#pragma unroll
            for (int j = 0; j < CPT; j++) wv[j] = sW[k][tx * CPT + j];
#pragma unroll
            for (int i = 0; i < RPT; i++) {
                float xv = sX[ty * RPT + i][k];
#pragma unroll
                for (int j = 0; j < CPT; j++) acc[i][j] += xv * wv[j];
            }
        }
        __syncthreads();
    }

#pragma unroll
    for (int i = 0; i < RPT; i++) {
        int gr = row0 + ty * RPT + i;
        if (gr < NN) {
#pragma unroll
            for (int j = 0; j < CPT; j++)
                Y[(size_t)gr * NC + tx * CPT + j] = acc[i][j];
        }
    }
}

// ---------------- aggregation: one warp per node ----------------
// hs2 = relu(sum_{e in in(n)} Y[src_e] * dst_norm + b1) * src_norm  (layer 1, 128 cols)
__global__ __launch_bounds__(256) void k_agg128(const float* __restrict__ Y,
                                                const float* __restrict__ bias) {
    int node = (blockIdx.x * blockDim.x + threadIdx.x) >> 5;
    if (node >= NN) return;
    int lane = threadIdx.x & 31;
    int beg = g_row_off[node], end = g_row_off[node + 1];
    float4 acc = make_float4(0.f, 0.f, 0.f, 0.f);
    for (int e = beg; e < end; e++) {
        int s = g_csr_src[e];
        float4 v = __ldg((const float4*)(Y + (size_t)s * 128) + lane);
        acc.x += v.x; acc.y += v.y; acc.z += v.z; acc.w += v.w;
    }
    float dn = g_dst_norm[node];
    float ps = g_src_norm[node];
    float4 b = ((const float4*)bias)[lane];
    float4 o;
    o.x = fmaxf(acc.x * dn + b.x, 0.f) * ps;
    o.y = fmaxf(acc.y * dn + b.y, 0.f) * ps;
    o.z = fmaxf(acc.z * dn + b.z, 0.f) * ps;
    o.w = fmaxf(acc.w * dn + b.w, 0.f) * ps;
    ((float4*)(g_hs2 + (size_t)node * 128))[lane] = o;
}

// out = sum Y[src] * dst_norm + b2   (layer 2, 40 cols)
__global__ __launch_bounds__(256) void k_agg40(const float* __restrict__ Y,
                                               const float* __restrict__ bias,
                                               float* __restrict__ out) {
    int node = (blockIdx.x * blockDim.x + threadIdx.x) >> 5;
    if (node >= NN) return;
    int lane = threadIdx.x & 31;
    int beg = g_row_off[node], end = g_row_off[node + 1];
    float acc0 = 0.f, acc1 = 0.f;
    for (int e = beg; e < end; e++) {
        int s = g_csr_src[e];
        const float* row = Y + (size_t)s * FC;
        acc0 += __ldg(row + lane);
        if (lane < 8) acc1 += __ldg(row + lane + 32);
    }
    float dn = g_dst_norm[node];
    out[(size_t)node * FC + lane] = acc0 * dn + bias[lane];
    if (lane < 8)
        out[(size_t)node * FC + lane + 32] = acc1 * dn + bias[lane + 32];
}

// ---------------- launch ----------------
extern "C" void kernel_launch(void* const* d_in, const int* in_sizes, int n_in,
                              void* d_out, int out_size) {
    const float* x   = (const float*)d_in[0];
    const float* W1  = (const float*)d_in[1];
    const float* b1  = (const float*)d_in[2];
    const float* W2  = (const float*)d_in[3];
    const float* b2  = (const float*)d_in[4];
    const int*   src = (const int*)  d_in[5];
    const int*   dst = (const int*)  d_in[6];
    float* out = (float*)d_out;

    float *xw, *hs2, *hw, *sn;
    cudaGetSymbolAddress((void**)&xw,  g_xw);
    cudaGetSymbolAddress((void**)&hs2, g_hs2);
    cudaGetSymbolAddress((void**)&hw,  g_hw);
    cudaGetSymbolAddress((void**)&sn,  g_src_norm);

    // --- CSR + norms ---
    k_zero<<<(NN + 255) / 256, 256>>>();
    k_hist<<<(NE + 255) / 256, 256>>>(src, dst);
    k_scan<<<1, 1024>>>();
    k_norm<<<(NN + 255) / 256, 256>>>();
    k_fill<<<(NE + 255) / 256, 256>>>(src, dst);

    // --- layer 1: GEMM (weight-first) then aggregate ---
    k_gemm<128, 16, 8, 4><<<(NN + 63) / 64, 256>>>(x, W1, sn, xw);
    k_agg128<<<(NN * 32 + 255) / 256, 256>>>(xw, b1);

    // --- layer 2 ---
    k_gemm<40, 8, 5, 2><<<(NN + 63) / 64, 256>>>(hs2, W2, nullptr, hw);
    k_agg40<<<(NN * 32 + 255) / 256, 256>>>(hw, b2, out);
}

// round 4
// speedup vs baseline: 1.1432x; 1.1432x over previous
#include <cuda_runtime.h>
#include <cuda_bf16.h>

// Problem constants (fixed by the reference)
#define NN 100000
#define NE 1600000
#define FIN 128
#define FH  128
#define FC  40

// packed fp32x2 ops (Blackwell sm_103a; ptxas never emits these from C++)
#define FMA_F32X2(d, a, b, c) \
    asm("fma.rn.f32x2 %0, %1, %2, %3;" : "=l"(d) : "l"(a), "l"(b), "l"(c))
#define PACK_DUP_F32(d, s) \
    asm("mov.b64 %0, {%1, %1};" : "=l"(d) : "f"(s))

// ---------------- device scratch (no allocs allowed) ----------------
__device__ int   g_deg_out[NN];
__device__ int   g_deg_in[NN];
__device__ int   g_fill[NN];          // fill cursor (init = row_off)
__device__ int   g_row_off[NN + 1];
__device__ int   g_csr_src[NE];
__device__ float g_src_norm[NN];
__device__ float g_dst_norm[NN];
__device__ float g_xw [(size_t)NN * FH];   // x @ W1 (no norm yet)
__device__ float g_hs2[(size_t)NN * FH];   // relu(agg*dn + b1) * src_norm
__device__ float g_hw [(size_t)NN * FC];   // hs2 @ W2

// ---------------- setup kernels ----------------
__global__ __launch_bounds__(256) void k_zero() {
    int i = blockIdx.x * blockDim.x + threadIdx.x;
    if (i < NN) { g_deg_out[i] = 0; g_deg_in[i] = 0; }
}

__global__ __launch_bounds__(256) void k_hist(const int* __restrict__ src,
                                              const int* __restrict__ dst) {
    int e = blockIdx.x * blockDim.x + threadIdx.x;
    if (e < NE) {
        atomicAdd(&g_deg_out[src[e]], 1);
        atomicAdd(&g_deg_in [dst[e]], 1);
    }
}

// single-block exclusive scan of g_deg_in -> g_row_off (N=100000)
__global__ __launch_bounds__(1024) void k_scan() {
    __shared__ int ssum[1024];
    const int CH = (NN + 1023) / 1024;   // 98
    int tid = threadIdx.x;
    int base = tid * CH;
    int s = 0;
    for (int i = 0; i < CH; i++) {
        int idx = base + i;
        if (idx < NN) s += g_deg_in[idx];
    }
    ssum[tid] = s;
    __syncthreads();
    for (int d = 1; d < 1024; d <<= 1) {
        int v = (tid >= d) ? ssum[tid - d] : 0;
        __syncthreads();
        ssum[tid] += v;
        __syncthreads();
    }
    int run = (tid == 0) ? 0 : ssum[tid - 1];
    for (int i = 0; i < CH; i++) {
        int idx = base + i;
        if (idx < NN) { g_row_off[idx] = run; run += g_deg_in[idx]; }
    }
    if (tid == 1023) g_row_off[NN] = ssum[1023];
}

__global__ __launch_bounds__(256) void k_norm() {
    int i = blockIdx.x * blockDim.x + threadIdx.x;
    if (i < NN) {
        g_src_norm[i] = rsqrtf((float)max(g_deg_out[i], 1));
        g_dst_norm[i] = rsqrtf((float)max(g_deg_in [i], 1));
        g_fill[i] = g_row_off[i];      // fill cursor
    }
}

__global__ __launch_bounds__(256) void k_fill(const int* __restrict__ src,
                                              const int* __restrict__ dst) {
    int e = blockIdx.x * blockDim.x + threadIdx.x;
    if (e < NE) {
        int p = atomicAdd(&g_fill[dst[e]], 1);
        g_csr_src[p] = src[e];
    }
}

// ---------------- dense GEMM: Y[M,NC] = X[M,128] @ W[128,NC], fp32x2 packed
// 256 threads, BM=128 rows/block, K tiled by 32.
// Thread computes RPT rows x (CPT2*2) cols via fma.rn.f32x2.
template<int NC, int TX, int CPT2, int RPT>
__global__ __launch_bounds__(256) void k_gemm(const float* __restrict__ X,
                                              const float* __restrict__ W,
                                              float* __restrict__ Y) {
    static_assert(TX * CPT2 * 2 == NC, "cols");
    static_assert((256 / TX) * RPT == 128, "rows");
    const int BM = 128, KT = 32;
    __shared__ __align__(16) float sW[KT][NC];      // KT*NC floats
    __shared__ __align__(16) float sX[BM][KT + 1];  // pad kills conflicts

    int tid  = threadIdx.x;
    int row0 = blockIdx.x * BM;
    int tx = tid % TX, ty = tid / TX;

    unsigned long long acc[RPT][CPT2];
#pragma unroll
    for (int i = 0; i < RPT; i++)
#pragma unroll
        for (int j = 0; j < CPT2; j++) acc[i][j] = 0ull;

    for (int kt = 0; kt < 128; kt += KT) {
        for (int i = tid; i < KT * NC; i += 256)
            sW[i / NC][i % NC] = W[(size_t)(kt + i / NC) * NC + (i % NC)];
        for (int i = tid; i < BM * KT; i += 256) {
            int r = i >> 5, c = i & 31;
            int gr = row0 + r;
            sX[r][c] = (gr < NN) ? X[(size_t)gr * 128 + kt + c] : 0.f;
        }
        __syncthreads();

#pragma unroll 8
        for (int k = 0; k < KT; k++) {
            unsigned long long w2[CPT2];
#pragma unroll
            for (int j = 0; j < CPT2; j++)
                w2[j] = *(const unsigned long long*)&sW[k][tx * CPT2 * 2 + 2 * j];
#pragma unroll
            for (int i = 0; i < RPT; i++) {
                float xv = sX[ty * RPT + i][k];
                unsigned long long xx;
                PACK_DUP_F32(xx, xv);
#pragma unroll
                for (int j = 0; j < CPT2; j++)
                    FMA_F32X2(acc[i][j], xx, w2[j], acc[i][j]);
            }
        }
        __syncthreads();
    }

#pragma unroll
    for (int i = 0; i < RPT; i++) {
        int gr = row0 + ty * RPT + i;
        if (gr < NN) {
#pragma unroll
            for (int j = 0; j < CPT2; j++)
                *(unsigned long long*)&Y[(size_t)gr * NC + tx * CPT2 * 2 + 2 * j]
                    = acc[i][j];
        }
    }
}

// ---------------- aggregation: one warp per node ----------------
// hs2 = relu( (sum_e xw[src_e]*src_norm[src_e]) * dst_norm + b1 ) * src_norm[node]
__global__ __launch_bounds__(256) void k_agg128(const float* __restrict__ Y,
                                                const float* __restrict__ bias) {
    int node = (blockIdx.x * blockDim.x + threadIdx.x) >> 5;
    if (node >= NN) return;
    int lane = threadIdx.x & 31;
    int beg = g_row_off[node], end = g_row_off[node + 1];
    float4 acc = make_float4(0.f, 0.f, 0.f, 0.f);
    for (int e = beg; e < end; e++) {
        int s = g_csr_src[e];
        float sn = __ldg(&g_src_norm[s]);          // warp-broadcast load
        float4 v = __ldg((const float4*)(Y + (size_t)s * 128) + lane);
        acc.x = fmaf(v.x, sn, acc.x);
        acc.y = fmaf(v.y, sn, acc.y);
        acc.z = fmaf(v.z, sn, acc.z);
        acc.w = fmaf(v.w, sn, acc.w);
    }
    float dn = g_dst_norm[node];
    float ps = g_src_norm[node];
    float4 b = ((const float4*)bias)[lane];
    float4 o;
    o.x = fmaxf(fmaf(acc.x, dn, b.x), 0.f) * ps;
    o.y = fmaxf(fmaf(acc.y, dn, b.y), 0.f) * ps;
    o.z = fmaxf(fmaf(acc.z, dn, b.z), 0.f) * ps;
    o.w = fmaxf(fmaf(acc.w, dn, b.w), 0.f) * ps;
    ((float4*)(g_hs2 + (size_t)node * 128))[lane] = o;
}

// out = (sum_e hw[src_e]) * dst_norm + b2   (layer 2, 40 cols)
__global__ __launch_bounds__(256) void k_agg40(const float* __restrict__ Y,
                                               const float* __restrict__ bias,
                                               float* __restrict__ out) {
    int node = (blockIdx.x * blockDim.x + threadIdx.x) >> 5;
    if (node >= NN) return;
    int lane = threadIdx.x & 31;
    int beg = g_row_off[node], end = g_row_off[node + 1];
    float acc0 = 0.f, acc1 = 0.f;
    for (int e = beg; e < end; e++) {
        int s = g_csr_src[e];
        const float* row = Y + (size_t)s * FC;
        acc0 += __ldg(row + lane);
        if (lane < 8) acc1 += __ldg(row + lane + 32);
    }
    float dn = g_dst_norm[node];
    out[(size_t)node * FC + lane] = fmaf(acc0, dn, bias[lane]);
    if (lane < 8)
        out[(size_t)node * FC + lane + 32] = fmaf(acc1, dn, bias[lane + 32]);
}

// ---------------- launch ----------------
extern "C" void kernel_launch(void* const* d_in, const int* in_sizes, int n_in,
                              void* d_out, int out_size) {
    const float* x   = (const float*)d_in[0];
    const float* W1  = (const float*)d_in[1];
    const float* b1  = (const float*)d_in[2];
    const float* W2  = (const float*)d_in[3];
    const float* b2  = (const float*)d_in[4];
    const int*   src = (const int*)  d_in[5];
    const int*   dst = (const int*)  d_in[6];
    float* out = (float*)d_out;

    float *xw, *hs2, *hw;
    cudaGetSymbolAddress((void**)&xw,  g_xw);
    cudaGetSymbolAddress((void**)&hs2, g_hs2);
    cudaGetSymbolAddress((void**)&hw,  g_hw);

    // fork: GEMM1 (pure compute, independent of graph structure) runs on a
    // side stream concurrently with the CSR-build chain on the main stream.
    cudaStream_t s2;
    cudaStreamCreateWithFlags(&s2, cudaStreamNonBlocking);
    cudaEvent_t eFork, eJoin;
    cudaEventCreateWithFlags(&eFork, cudaEventDisableTiming);
    cudaEventCreateWithFlags(&eJoin, cudaEventDisableTiming);

    cudaEventRecord(eFork, 0);
    cudaStreamWaitEvent(s2, eFork, 0);

    // side stream: layer-1 GEMM (weight-first, norms applied later per-edge)
    k_gemm<128, 16, 4, 8><<<(NN + 127) / 128, 256, 0, s2>>>(x, W1, xw);
    cudaEventRecord(eJoin, s2);

    // main stream: CSR + norms
    k_zero<<<(NN + 255) / 256, 256>>>();
    k_hist<<<(NE + 255) / 256, 256>>>(src, dst);
    k_scan<<<1, 1024>>>();
    k_norm<<<(NN + 255) / 256, 256>>>();
    k_fill<<<(NE + 255) / 256, 256>>>(src, dst);

    // join
    cudaStreamWaitEvent(0, eJoin, 0);

    // layer-1 aggregate (+ relu + fold layer-2 src norm)
    k_agg128<<<(NN * 32 + 255) / 256, 256>>>(xw, b1);

    // layer 2
    k_gemm<40, 4, 5, 2><<<(NN + 127) / 128, 256>>>(hs2, W2, hw);
    k_agg40<<<(NN * 32 + 255) / 256, 256>>>(hw, b2, out);

    cudaEventDestroy(eFork);
    cudaEventDestroy(eJoin);
    cudaStreamDestroy(s2);
}

// round 5
// speedup vs baseline: 1.5791x; 1.3813x over previous
#include <cuda_runtime.h>
#include <cuda_bf16.h>

// Problem constants (fixed by the reference)
#define NN 100000
#define NE 1600000
#define FIN 128
#define FH  128
#define FC  40

#define NI4 (NN / 4)            // 25000 int4 chunks (NN divisible by 4)
#define SCAN_BLKS ((NI4 + 255) / 256)   // 98

// packed fp32x2 ops (Blackwell sm_103a; ptxas never emits these from C++)
#define FMA_F32X2(d, a, b, c) \
    asm("fma.rn.f32x2 %0, %1, %2, %3;" : "=l"(d) : "l"(a), "l"(b), "l"(c))
#define PACK_DUP_F32(d, s) \
    asm("mov.b64 %0, {%1, %1};" : "=l"(d) : "f"(s))

// ---------------- device scratch (no allocs allowed) ----------------
__device__ __align__(16) int   g_deg_out[NN];
__device__ __align__(16) int   g_deg_in[NN];
__device__ __align__(16) int   g_fill[NN];          // fill cursor (init = row_off)
__device__ __align__(16) int   g_row_off[NN + 4];
__device__ int   g_part[SCAN_BLKS];
__device__ int   g_poff[SCAN_BLKS];
__device__ __align__(16) float g_src_norm[NN];
__device__ __align__(16) float g_dst_norm[NN];
__device__ int   g_csr_src[NE];
__device__ float g_xw [(size_t)NN * FH];   // x @ W1 (no norm yet)
__device__ float g_hs2[(size_t)NN * FH];   // relu(agg*dn + b1) * src_norm
__device__ float g_hw [(size_t)NN * FC];   // hs2 @ W2

// ---------------- setup kernels ----------------
__global__ __launch_bounds__(256) void k_zero() {
    int i = blockIdx.x * blockDim.x + threadIdx.x;
    if (i < NN) { g_deg_out[i] = 0; g_deg_in[i] = 0; }
}

__global__ __launch_bounds__(256) void k_hist(const int* __restrict__ src,
                                              const int* __restrict__ dst) {
    int e = blockIdx.x * blockDim.x + threadIdx.x;
    if (e < NE) {
        atomicAdd(&g_deg_out[__ldg(src + e)], 1);
        atomicAdd(&g_deg_in [__ldg(dst + e)], 1);
    }
}

// ---- 3-phase exclusive scan of g_deg_in (NN elems) -> g_row_off ----
// Phase A: per-block sums (int4 loads)
__global__ __launch_bounds__(256) void k_scanA() {
    int t = threadIdx.x;
    int i4 = blockIdx.x * 256 + t;
    int s = 0;
    if (i4 < NI4) {
        int4 v = ((const int4*)g_deg_in)[i4];
        s = v.x + v.y + v.z + v.w;
    }
#pragma unroll
    for (int d = 16; d; d >>= 1) s += __shfl_down_sync(0xffffffffu, s, d);
    __shared__ int ws[8];
    if ((t & 31) == 0) ws[t >> 5] = s;
    __syncthreads();
    if (t == 0) {
        int tot = 0;
#pragma unroll
        for (int w = 0; w < 8; w++) tot += ws[w];
        g_part[blockIdx.x] = tot;
    }
}

// Phase B: scan the 98 partials in one tiny block
__global__ __launch_bounds__(128) void k_scanB() {
    __shared__ int sm[128];
    int t = threadIdx.x;
    int v = (t < SCAN_BLKS) ? g_part[t] : 0;
    sm[t] = v;
    __syncthreads();
#pragma unroll
    for (int d = 1; d < 128; d <<= 1) {
        int u = (t >= d) ? sm[t - d] : 0;
        __syncthreads();
        sm[t] += u;
        __syncthreads();
    }
    if (t < SCAN_BLKS) g_poff[t] = (t == 0) ? 0 : sm[t - 1];
    if (t == 0) g_row_off[NN] = NE;   // every edge's dst is in [0,NN)
}

// Phase C: block-local exclusive scan + offset; fused norms + fill cursor
__global__ __launch_bounds__(256) void k_scanC() {
    int t = threadIdx.x;
    int i4 = blockIdx.x * 256 + t;
    bool ok = i4 < NI4;
    int4 v = make_int4(0, 0, 0, 0);
    if (ok) v = ((const int4*)g_deg_in)[i4];
    int tsum = v.x + v.y + v.z + v.w;

    int lane = t & 31, w = t >> 5;
    int incl = tsum;
#pragma unroll
    for (int d = 1; d < 32; d <<= 1) {
        int u = __shfl_up_sync(0xffffffffu, incl, d);
        if (lane >= d) incl += u;
    }
    __shared__ int wsum[8], woff[8];
    if (lane == 31) wsum[w] = incl;
    __syncthreads();
    if (t < 8) {
        int r = 0;
        for (int k = 0; k < t; k++) r += wsum[k];
        woff[t] = r;
    }
    __syncthreads();

    if (ok) {
        int off = g_poff[blockIdx.x] + woff[w] + (incl - tsum);
        int4 ro;
        ro.x = off;
        ro.y = ro.x + v.x;
        ro.z = ro.y + v.y;
        ro.w = ro.z + v.z;
        ((int4*)g_row_off)[i4] = ro;
        ((int4*)g_fill)[i4]    = ro;
        float4 dn;
        dn.x = rsqrtf((float)max(v.x, 1));
        dn.y = rsqrtf((float)max(v.y, 1));
        dn.z = rsqrtf((float)max(v.z, 1));
        dn.w = rsqrtf((float)max(v.w, 1));
        ((float4*)g_dst_norm)[i4] = dn;
        int4 o = ((const int4*)g_deg_out)[i4];
        float4 sn;
        sn.x = rsqrtf((float)max(o.x, 1));
        sn.y = rsqrtf((float)max(o.y, 1));
        sn.z = rsqrtf((float)max(o.z, 1));
        sn.w = rsqrtf((float)max(o.w, 1));
        ((float4*)g_src_norm)[i4] = sn;
    }
}

__global__ __launch_bounds__(256) void k_fill(const int* __restrict__ src,
                                              const int* __restrict__ dst) {
    int e = blockIdx.x * blockDim.x + threadIdx.x;
    if (e < NE) {
        int p = atomicAdd(&g_fill[__ldg(dst + e)], 1);
        g_csr_src[p] = __ldg(src + e);
    }
}

// ---------------- dense GEMM: Y[M,NC] = X[M,128] @ W[128,NC], fp32x2 packed
template<int NC, int TX, int CPT2, int RPT>
__global__ __launch_bounds__(256) void k_gemm(const float* __restrict__ X,
                                              const float* __restrict__ W,
                                              float* __restrict__ Y) {
    static_assert(TX * CPT2 * 2 == NC, "cols");
    static_assert((256 / TX) * RPT == 128, "rows");
    const int BM = 128, KT = 32;
    __shared__ __align__(16) float sW[KT][NC];
    __shared__ __align__(16) float sX[BM][KT + 1];

    int tid  = threadIdx.x;
    int row0 = blockIdx.x * BM;
    int tx = tid % TX, ty = tid / TX;

    unsigned long long acc[RPT][CPT2];
#pragma unroll
    for (int i = 0; i < RPT; i++)
#pragma unroll
        for (int j = 0; j < CPT2; j++) acc[i][j] = 0ull;

    for (int kt = 0; kt < 128; kt += KT) {
        for (int i = tid; i < KT * NC; i += 256)
            sW[i / NC][i % NC] = W[(size_t)(kt + i / NC) * NC + (i % NC)];
        for (int i = tid; i < BM * KT; i += 256) {
            int r = i >> 5, c = i & 31;
            int gr = row0 + r;
            sX[r][c] = (gr < NN) ? X[(size_t)gr * 128 + kt + c] : 0.f;
        }
        __syncthreads();

#pragma unroll 8
        for (int k = 0; k < KT; k++) {
            unsigned long long w2[CPT2];
#pragma unroll
            for (int j = 0; j < CPT2; j++)
                w2[j] = *(const unsigned long long*)&sW[k][tx * CPT2 * 2 + 2 * j];
#pragma unroll
            for (int i = 0; i < RPT; i++) {
                float xv = sX[ty * RPT + i][k];
                unsigned long long xx;
                PACK_DUP_F32(xx, xv);
#pragma unroll
                for (int j = 0; j < CPT2; j++)
                    FMA_F32X2(acc[i][j], xx, w2[j], acc[i][j]);
            }
        }
        __syncthreads();
    }

#pragma unroll
    for (int i = 0; i < RPT; i++) {
        int gr = row0 + ty * RPT + i;
        if (gr < NN) {
#pragma unroll
            for (int j = 0; j < CPT2; j++)
                *(unsigned long long*)&Y[(size_t)gr * NC + tx * CPT2 * 2 + 2 * j]
                    = acc[i][j];
        }
    }
}

// ---------------- aggregation: one warp per node ----------------
__global__ __launch_bounds__(256) void k_agg128(const float* __restrict__ Y,
                                                const float* __restrict__ bias) {
    int node = (blockIdx.x * blockDim.x + threadIdx.x) >> 5;
    if (node >= NN) return;
    int lane = threadIdx.x & 31;
    int beg = g_row_off[node], end = g_row_off[node + 1];
    float4 acc = make_float4(0.f, 0.f, 0.f, 0.f);
    for (int e = beg; e < end; e++) {
        int s = g_csr_src[e];
        float sn = __ldg(&g_src_norm[s]);          // warp-broadcast load
        float4 v = __ldg((const float4*)(Y + (size_t)s * 128) + lane);
        acc.x = fmaf(v.x, sn, acc.x);
        acc.y = fmaf(v.y, sn, acc.y);
        acc.z = fmaf(v.z, sn, acc.z);
        acc.w = fmaf(v.w, sn, acc.w);
    }
    float dn = g_dst_norm[node];
    float ps = g_src_norm[node];
    float4 b = ((const float4*)bias)[lane];
    float4 o;
    o.x = fmaxf(fmaf(acc.x, dn, b.x), 0.f) * ps;
    o.y = fmaxf(fmaf(acc.y, dn, b.y), 0.f) * ps;
    o.z = fmaxf(fmaf(acc.z, dn, b.z), 0.f) * ps;
    o.w = fmaxf(fmaf(acc.w, dn, b.w), 0.f) * ps;
    ((float4*)(g_hs2 + (size_t)node * 128))[lane] = o;
}

__global__ __launch_bounds__(256) void k_agg40(const float* __restrict__ Y,
                                               const float* __restrict__ bias,
                                               float* __restrict__ out) {
    int node = (blockIdx.x * blockDim.x + threadIdx.x) >> 5;
    if (node >= NN) return;
    int lane = threadIdx.x & 31;
    int beg = g_row_off[node], end = g_row_off[node + 1];
    float acc0 = 0.f, acc1 = 0.f;
    for (int e = beg; e < end; e++) {
        int s = g_csr_src[e];
        const float* row = Y + (size_t)s * FC;
        acc0 += __ldg(row + lane);
        if (lane < 8) acc1 += __ldg(row + lane + 32);
    }
    float dn = g_dst_norm[node];
    out[(size_t)node * FC + lane] = fmaf(acc0, dn, bias[lane]);
    if (lane < 8)
        out[(size_t)node * FC + lane + 32] = fmaf(acc1, dn, bias[lane + 32]);
}

// ---------------- launch ----------------
extern "C" void kernel_launch(void* const* d_in, const int* in_sizes, int n_in,
                              void* d_out, int out_size) {
    const float* x   = (const float*)d_in[0];
    const float* W1  = (const float*)d_in[1];
    const float* b1  = (const float*)d_in[2];
    const float* W2  = (const float*)d_in[3];
    const float* b2  = (const float*)d_in[4];
    const int*   src = (const int*)  d_in[5];
    const int*   dst = (const int*)  d_in[6];
    float* out = (float*)d_out;

    float *xw, *hs2, *hw;
    cudaGetSymbolAddress((void**)&xw,  g_xw);
    cudaGetSymbolAddress((void**)&hs2, g_hs2);
    cudaGetSymbolAddress((void**)&hw,  g_hw);

    // fork: GEMM1 (independent of graph structure) overlaps the CSR chain
    cudaStream_t s2;
    cudaStreamCreateWithFlags(&s2, cudaStreamNonBlocking);
    cudaEvent_t eFork, eJoin;
    cudaEventCreateWithFlags(&eFork, cudaEventDisableTiming);
    cudaEventCreateWithFlags(&eJoin, cudaEventDisableTiming);

    cudaEventRecord(eFork, 0);
    cudaStreamWaitEvent(s2, eFork, 0);

    k_gemm<128, 16, 4, 8><<<(NN + 127) / 128, 256, 0, s2>>>(x, W1, xw);
    cudaEventRecord(eJoin, s2);

    // main stream: CSR + norms (scan is now 3 tiny whole-grid kernels)
    k_zero<<<(NN + 255) / 256, 256>>>();
    k_hist<<<(NE + 255) / 256, 256>>>(src, dst);
    k_scanA<<<SCAN_BLKS, 256>>>();
    k_scanB<<<1, 128>>>();
    k_scanC<<<SCAN_BLKS, 256>>>();
    k_fill<<<(NE + 255) / 256, 256>>>(src, dst);

    cudaStreamWaitEvent(0, eJoin, 0);

    k_agg128<<<(NN * 32 + 255) / 256, 256>>>(xw, b1);

    k_gemm<40, 4, 5, 2><<<(NN + 127) / 128, 256>>>(hs2, W2, hw);
    k_agg40<<<(NN * 32 + 255) / 256, 256>>>(hw, b2, out);

    cudaEventDestroy(eFork);
    cudaEventDestroy(eJoin);
    cudaStreamDestroy(s2);
}

// round 6
// speedup vs baseline: 1.6304x; 1.0325x over previous
#include <cuda_runtime.h>
#include <cuda_bf16.h>

// Problem constants (fixed by the reference)
#define NN 100000
#define NE 1600000
#define FIN 128
#define FH  128
#define FC  40

#define NI4 (NN / 4)            // 25000 int4 chunks (NN divisible by 4)
#define SCAN_BLKS ((NI4 + 255) / 256)   // 98

// packed fp32x2 ops (Blackwell sm_103a; ptxas never emits these from C++)
#define FMA_F32X2(d, a, b, c) \
    asm("fma.rn.f32x2 %0, %1, %2, %3;" : "=l"(d) : "l"(a), "l"(b), "l"(c))
#define PACK_DUP_F32(d, s) \
    asm("mov.b64 %0, {%1, %1};" : "=l"(d) : "f"(s))

// ---------------- device scratch (no allocs allowed) ----------------
__device__ __align__(16) int   g_deg_out[NN];
__device__ __align__(16) int   g_deg_in[NN];
__device__ __align__(16) int   g_fill[NN];          // fill cursor (init = row_off)
__device__ __align__(16) int   g_row_off[NN + 4];
__device__ int   g_part[SCAN_BLKS];
__device__ int   g_poff[SCAN_BLKS];
__device__ __align__(16) float g_src_norm[NN];
__device__ __align__(16) float g_dst_norm[NN];
__device__ int   g_csr_src[NE];
__device__ float g_xw [(size_t)NN * FH];   // x @ W1 (no norm yet)
__device__ float g_hs2[(size_t)NN * FH];   // relu(agg*dn + b1) * src_norm
__device__ float g_hw [(size_t)NN * FC];   // hs2 @ W2

// ---------------- setup kernels ----------------
__global__ __launch_bounds__(256) void k_zero() {
    int i = blockIdx.x * blockDim.x + threadIdx.x;
    if (i < NN) { g_deg_out[i] = 0; g_deg_in[i] = 0; }
}

__global__ __launch_bounds__(256) void k_hist(const int* __restrict__ src,
                                              const int* __restrict__ dst) {
    int e = blockIdx.x * blockDim.x + threadIdx.x;
    if (e < NE) {
        atomicAdd(&g_deg_out[__ldg(src + e)], 1);
        atomicAdd(&g_deg_in [__ldg(dst + e)], 1);
    }
}

// ---- 3-phase exclusive scan of g_deg_in (NN elems) -> g_row_off ----
// Phase A: per-block sums (int4 loads)
__global__ __launch_bounds__(256) void k_scanA() {
    int t = threadIdx.x;
    int i4 = blockIdx.x * 256 + t;
    int s = 0;
    if (i4 < NI4) {
        int4 v = ((const int4*)g_deg_in)[i4];
        s = v.x + v.y + v.z + v.w;
    }
#pragma unroll
    for (int d = 16; d; d >>= 1) s += __shfl_down_sync(0xffffffffu, s, d);
    __shared__ int ws[8];
    if ((t & 31) == 0) ws[t >> 5] = s;
    __syncthreads();
    if (t == 0) {
        int tot = 0;
#pragma unroll
        for (int w = 0; w < 8; w++) tot += ws[w];
        g_part[blockIdx.x] = tot;
    }
}

// Phase B: scan the 98 partials in one tiny block
__global__ __launch_bounds__(128) void k_scanB() {
    __shared__ int sm[128];
    int t = threadIdx.x;
    int v = (t < SCAN_BLKS) ? g_part[t] : 0;
    sm[t] = v;
    __syncthreads();
#pragma unroll
    for (int d = 1; d < 128; d <<= 1) {
        int u = (t >= d) ? sm[t - d] : 0;
        __syncthreads();
        sm[t] += u;
        __syncthreads();
    }
    if (t < SCAN_BLKS) g_poff[t] = (t == 0) ? 0 : sm[t - 1];
    if (t == 0) g_row_off[NN] = NE;   // every edge's dst is in [0,NN)
}

// Phase C: block-local exclusive scan + offset; fused norms + fill cursor
__global__ __launch_bounds__(256) void k_scanC() {
    int t = threadIdx.x;
    int i4 = blockIdx.x * 256 + t;
    bool ok = i4 < NI4;
    int4 v = make_int4(0, 0, 0, 0);
    if (ok) v = ((const int4*)g_deg_in)[i4];
    int tsum = v.x + v.y + v.z + v.w;

    int lane = t & 31, w = t >> 5;
    int incl = tsum;
#pragma unroll
    for (int d = 1; d < 32; d <<= 1) {
        int u = __shfl_up_sync(0xffffffffu, incl, d);
        if (lane >= d) incl += u;
    }
    __shared__ int wsum[8], woff[8];
    if (lane == 31) wsum[w] = incl;
    __syncthreads();
    if (t < 8) {
        int r = 0;
        for (int k = 0; k < t; k++) r += wsum[k];
        woff[t] = r;
    }
    __syncthreads();

    if (ok) {
        int off = g_poff[blockIdx.x] + woff[w] + (incl - tsum);
        int4 ro;
        ro.x = off;
        ro.y = ro.x + v.x;
        ro.z = ro.y + v.y;
        ro.w = ro.z + v.z;
        ((int4*)g_row_off)[i4] = ro;
        ((int4*)g_fill)[i4]    = ro;
        float4 dn;
        dn.x = rsqrtf((float)max(v.x, 1));
        dn.y = rsqrtf((float)max(v.y, 1));
        dn.z = rsqrtf((float)max(v.z, 1));
        dn.w = rsqrtf((float)max(v.w, 1));
        ((float4*)g_dst_norm)[i4] = dn;
        int4 o = ((const int4*)g_deg_out)[i4];
        float4 sn;
        sn.x = rsqrtf((float)max(o.x, 1));
        sn.y = rsqrtf((float)max(o.y, 1));
        sn.z = rsqrtf((float)max(o.z, 1));
        sn.w = rsqrtf((float)max(o.w, 1));
        ((float4*)g_src_norm)[i4] = sn;
    }
}

__global__ __launch_bounds__(256) void k_fill(const int* __restrict__ src,
                                              const int* __restrict__ dst) {
    int e = blockIdx.x * blockDim.x + threadIdx.x;
    if (e < NE) {
        int p = atomicAdd(&g_fill[__ldg(dst + e)], 1);
        g_csr_src[p] = __ldg(src + e);
    }
}

// ---------------- dense GEMM: Y[M,NC] = X[M,128] @ W[128,NC], fp32x2 packed
template<int NC, int TX, int CPT2, int RPT>
__global__ __launch_bounds__(256) void k_gemm(const float* __restrict__ X,
                                              const float* __restrict__ W,
                                              float* __restrict__ Y) {
    static_assert(TX * CPT2 * 2 == NC, "cols");
    static_assert((256 / TX) * RPT == 128, "rows");
    const int BM = 128, KT = 32;
    __shared__ __align__(16) float sW[KT][NC];
    __shared__ __align__(16) float sX[BM][KT + 1];

    int tid  = threadIdx.x;
    int row0 = blockIdx.x * BM;
    int tx = tid % TX, ty = tid / TX;

    unsigned long long acc[RPT][CPT2];
#pragma unroll
    for (int i = 0; i < RPT; i++)
#pragma unroll
        for (int j = 0; j < CPT2; j++) acc[i][j] = 0ull;

    for (int kt = 0; kt < 128; kt += KT) {
        for (int i = tid; i < KT * NC; i += 256)
            sW[i / NC][i % NC] = W[(size_t)(kt + i / NC) * NC + (i % NC)];
        for (int i = tid; i < BM * KT; i += 256) {
            int r = i >> 5, c = i & 31;
            int gr = row0 + r;
            sX[r][c] = (gr < NN) ? X[(size_t)gr * 128 + kt + c] : 0.f;
        }
        __syncthreads();

#pragma unroll 8
        for (int k = 0; k < KT; k++) {
            unsigned long long w2[CPT2];
#pragma unroll
            for (int j = 0; j < CPT2; j++)
                w2[j] = *(const unsigned long long*)&sW[k][tx * CPT2 * 2 + 2 * j];
#pragma unroll
            for (int i = 0; i < RPT; i++) {
                float xv = sX[ty * RPT + i][k];
                unsigned long long xx;
                PACK_DUP_F32(xx, xv);
#pragma unroll
                for (int j = 0; j < CPT2; j++)
                    FMA_F32X2(acc[i][j], xx, w2[j], acc[i][j]);
            }
        }
        __syncthreads();
    }

#pragma unroll
    for (int i = 0; i < RPT; i++) {
        int gr = row0 + ty * RPT + i;
        if (gr < NN) {
#pragma unroll
            for (int j = 0; j < CPT2; j++)
                *(unsigned long long*)&Y[(size_t)gr * NC + tx * CPT2 * 2 + 2 * j]
                    = acc[i][j];
        }
    }
}

// ---------------- aggregation: one warp per node ----------------
__global__ __launch_bounds__(256) void k_agg128(const float* __restrict__ Y,
                                                const float* __restrict__ bias) {
    int node = (blockIdx.x * blockDim.x + threadIdx.x) >> 5;
    if (node >= NN) return;
    int lane = threadIdx.x & 31;
    int beg = g_row_off[node], end = g_row_off[node + 1];
    float4 acc = make_float4(0.f, 0.f, 0.f, 0.f);
    for (int e = beg; e < end; e++) {
        int s = g_csr_src[e];
        float sn = __ldg(&g_src_norm[s]);          // warp-broadcast load
        float4 v = __ldg((const float4*)(Y + (size_t)s * 128) + lane);
        acc.x = fmaf(v.x, sn, acc.x);
        acc.y = fmaf(v.y, sn, acc.y);
        acc.z = fmaf(v.z, sn, acc.z);
        acc.w = fmaf(v.w, sn, acc.w);
    }
    float dn = g_dst_norm[node];
    float ps = g_src_norm[node];
    float4 b = ((const float4*)bias)[lane];
    float4 o;
    o.x = fmaxf(fmaf(acc.x, dn, b.x), 0.f) * ps;
    o.y = fmaxf(fmaf(acc.y, dn, b.y), 0.f) * ps;
    o.z = fmaxf(fmaf(acc.z, dn, b.z), 0.f) * ps;
    o.w = fmaxf(fmaf(acc.w, dn, b.w), 0.f) * ps;
    ((float4*)(g_hs2 + (size_t)node * 128))[lane] = o;
}

__global__ __launch_bounds__(256) void k_agg40(const float* __restrict__ Y,
                                               const float* __restrict__ bias,
                                               float* __restrict__ out) {
    int node = (blockIdx.x * blockDim.x + threadIdx.x) >> 5;
    if (node >= NN) return;
    int lane = threadIdx.x & 31;
    int beg = g_row_off[node], end = g_row_off[node + 1];
    float acc0 = 0.f, acc1 = 0.f;
    for (int e = beg; e < end; e++) {
        int s = g_csr_src[e];
        const float* row = Y + (size_t)s * FC;
        acc0 += __ldg(row + lane);
        if (lane < 8) acc1 += __ldg(row + lane + 32);
    }
    float dn = g_dst_norm[node];
    out[(size_t)node * FC + lane] = fmaf(acc0, dn, bias[lane]);
    if (lane < 8)
        out[(size_t)node * FC + lane + 32] = fmaf(acc1, dn, bias[lane + 32]);
}

// ---------------- launch ----------------
extern "C" void kernel_launch(void* const* d_in, const int* in_sizes, int n_in,
                              void* d_out, int out_size) {
    const float* x   = (const float*)d_in[0];
    const float* W1  = (const float*)d_in[1];
    const float* b1  = (const float*)d_in[2];
    const float* W2  = (const float*)d_in[3];
    const float* b2  = (const float*)d_in[4];
    const int*   src = (const int*)  d_in[5];
    const int*   dst = (const int*)  d_in[6];
    float* out = (float*)d_out;

    float *xw, *hs2, *hw;
    cudaGetSymbolAddress((void**)&xw,  g_xw);
    cudaGetSymbolAddress((void**)&hs2, g_hs2);
    cudaGetSymbolAddress((void**)&hw,  g_hw);

    // fork: GEMM1 (independent of graph structure) overlaps the CSR chain
    cudaStream_t s2;
    cudaStreamCreateWithFlags(&s2, cudaStreamNonBlocking);
    cudaEvent_t eFork, eJoin;
    cudaEventCreateWithFlags(&eFork, cudaEventDisableTiming);
    cudaEventCreateWithFlags(&eJoin, cudaEventDisableTiming);

    cudaEventRecord(eFork, 0);
    cudaStreamWaitEvent(s2, eFork, 0);

    k_gemm<128, 16, 4, 8><<<(NN + 127) / 128, 256, 0, s2>>>(x, W1, xw);
    cudaEventRecord(eJoin, s2);

    // main stream: CSR + norms (scan is now 3 tiny whole-grid kernels)
    k_zero<<<(NN + 255) / 256, 256>>>();
    k_hist<<<(NE + 255) / 256, 256>>>(src, dst);
    k_scanA<<<SCAN_BLKS, 256>>>();
    k_scanB<<<1, 128>>>();
    k_scanC<<<SCAN_BLKS, 256>>>();
    k_fill<<<(NE + 255) / 256, 256>>>(src, dst);

    cudaStreamWaitEvent(0, eJoin, 0);

    k_agg128<<<(NN * 32 + 255) / 256, 256>>>(xw, b1);

    k_gemm<40, 4, 5, 2><<<(NN + 127) / 128, 256>>>(hs2, W2, hw);
    k_agg40<<<(NN * 32 + 255) / 256, 256>>>(hw, b2, out);

    cudaEventDestroy(eFork);
    cudaEventDestroy(eJoin);
    cudaStreamDestroy(s2);
}

// round 7
// speedup vs baseline: 1.8452x; 1.1317x over previous
#include <cuda_runtime.h>
#include <cuda_fp16.h>

// Problem constants (fixed by the reference)
#define NN 100000
#define NE 1600000
#define FIN 128
#define FH  128
#define FC  40

#define NI4 (NN / 4)                    // 25000 int4 chunks
#define SCAN_BLKS ((NI4 + 255) / 256)   // 98

// packed fp32x2 ops (Blackwell sm_103a; ptxas never emits these from C++)
#define FMA_F32X2(d, a, b, c) \
    asm("fma.rn.f32x2 %0, %1, %2, %3;" : "=l"(d) : "l"(a), "l"(b), "l"(c))
#define PACK_DUP_F32(d, s) \
    asm("mov.b64 %0, {%1, %1};" : "=l"(d) : "f"(s))

// ---------------- device scratch (no allocs allowed) ----------------
__device__ __align__(16) int   g_deg_out[NN];
__device__ __align__(16) int   g_deg_in[NN];
__device__ __align__(16) int   g_fill[NN];
__device__ __align__(16) int   g_row_off[NN + 4];
__device__ int   g_part[SCAN_BLKS];
__device__ int   g_poff[SCAN_BLKS];
__device__ __align__(16) float g_src_norm[NN];
__device__ __align__(16) float g_dst_norm[NN];
__device__ int   g_csr_src[NE];
__device__ __align__(16) __half g_xw [(size_t)NN * FH];  // x @ W1, fp16
__device__ __align__(16) float  g_hs2[(size_t)NN * FH];  // relu(...)·src_norm, fp32
__device__ __align__(16) __half g_hw [(size_t)NN * FC];  // hs2 @ W2, fp16

// ---------------- setup kernels ----------------
__global__ __launch_bounds__(256) void k_zero() {
    int i = blockIdx.x * blockDim.x + threadIdx.x;
    if (i < NN) { g_deg_out[i] = 0; g_deg_in[i] = 0; }
}

__global__ __launch_bounds__(256) void k_hist(const int* __restrict__ src,
                                              const int* __restrict__ dst) {
    int e = blockIdx.x * blockDim.x + threadIdx.x;
    if (e < NE) {
        atomicAdd(&g_deg_out[__ldg(src + e)], 1);
        atomicAdd(&g_deg_in [__ldg(dst + e)], 1);
    }
}

// ---- 3-phase exclusive scan of g_deg_in -> g_row_off ----
__global__ __launch_bounds__(256) void k_scanA() {
    int t = threadIdx.x;
    int i4 = blockIdx.x * 256 + t;
    int s = 0;
    if (i4 < NI4) {
        int4 v = ((const int4*)g_deg_in)[i4];
        s = v.x + v.y + v.z + v.w;
    }
#pragma unroll
    for (int d = 16; d; d >>= 1) s += __shfl_down_sync(0xffffffffu, s, d);
    __shared__ int ws[8];
    if ((t & 31) == 0) ws[t >> 5] = s;
    __syncthreads();
    if (t == 0) {
        int tot = 0;
#pragma unroll
        for (int w = 0; w < 8; w++) tot += ws[w];
        g_part[blockIdx.x] = tot;
    }
}

__global__ __launch_bounds__(128) void k_scanB() {
    __shared__ int sm[128];
    int t = threadIdx.x;
    int v = (t < SCAN_BLKS) ? g_part[t] : 0;
    sm[t] = v;
    __syncthreads();
#pragma unroll
    for (int d = 1; d < 128; d <<= 1) {
        int u = (t >= d) ? sm[t - d] : 0;
        __syncthreads();
        sm[t] += u;
        __syncthreads();
    }
    if (t < SCAN_BLKS) g_poff[t] = (t == 0) ? 0 : sm[t - 1];
    if (t == 0) g_row_off[NN] = NE;
}

__global__ __launch_bounds__(256) void k_scanC() {
    int t = threadIdx.x;
    int i4 = blockIdx.x * 256 + t;
    bool ok = i4 < NI4;
    int4 v = make_int4(0, 0, 0, 0);
    if (ok) v = ((const int4*)g_deg_in)[i4];
    int tsum = v.x + v.y + v.z + v.w;

    int lane = t & 31, w = t >> 5;
    int incl = tsum;
#pragma unroll
    for (int d = 1; d < 32; d <<= 1) {
        int u = __shfl_up_sync(0xffffffffu, incl, d);
        if (lane >= d) incl += u;
    }
    __shared__ int wsum[8], woff[8];
    if (lane == 31) wsum[w] = incl;
    __syncthreads();
    if (t < 8) {
        int r = 0;
        for (int k = 0; k < t; k++) r += wsum[k];
        woff[t] = r;
    }
    __syncthreads();

    if (ok) {
        int off = g_poff[blockIdx.x] + woff[w] + (incl - tsum);
        int4 ro;
        ro.x = off;
        ro.y = ro.x + v.x;
        ro.z = ro.y + v.y;
        ro.w = ro.z + v.z;
        ((int4*)g_row_off)[i4] = ro;
        ((int4*)g_fill)[i4]    = ro;
        float4 dn;
        dn.x = rsqrtf((float)max(v.x, 1));
        dn.y = rsqrtf((float)max(v.y, 1));
        dn.z = rsqrtf((float)max(v.z, 1));
        dn.w = rsqrtf((float)max(v.w, 1));
        ((float4*)g_dst_norm)[i4] = dn;
        int4 o = ((const int4*)g_deg_out)[i4];
        float4 sn;
        sn.x = rsqrtf((float)max(o.x, 1));
        sn.y = rsqrtf((float)max(o.y, 1));
        sn.z = rsqrtf((float)max(o.z, 1));
        sn.w = rsqrtf((float)max(o.w, 1));
        ((float4*)g_src_norm)[i4] = sn;
    }
}

__global__ __launch_bounds__(256) void k_fill(const int* __restrict__ src,
                                              const int* __restrict__ dst) {
    int e = blockIdx.x * blockDim.x + threadIdx.x;
    if (e < NE) {
        int p = atomicAdd(&g_fill[__ldg(dst + e)], 1);
        g_csr_src[p] = __ldg(src + e);
    }
}

// ---------------- dense GEMM: Y[M,NC] = X[M,128] @ W[128,NC], fp32x2 packed
// Output type OT: float (fp32 rows) or __half (fp16 rows).
template<int NC, int TX, int CPT2, int RPT, typename OT>
__global__ __launch_bounds__(256) void k_gemm(const float* __restrict__ X,
                                              const float* __restrict__ W,
                                              OT* __restrict__ Y) {
    static_assert(TX * CPT2 * 2 == NC, "cols");
    static_assert((256 / TX) * RPT == 128, "rows");
    const int BM = 128, KT = 32;
    __shared__ __align__(16) float sW[KT][NC];
    __shared__ __align__(16) float sX[BM][KT + 1];

    int tid  = threadIdx.x;
    int row0 = blockIdx.x * BM;
    int tx = tid % TX, ty = tid / TX;

    unsigned long long acc[RPT][CPT2];
#pragma unroll
    for (int i = 0; i < RPT; i++)
#pragma unroll
        for (int j = 0; j < CPT2; j++) acc[i][j] = 0ull;

    for (int kt = 0; kt < 128; kt += KT) {
        for (int i = tid; i < KT * NC; i += 256)
            sW[i / NC][i % NC] = W[(size_t)(kt + i / NC) * NC + (i % NC)];
        for (int i = tid; i < BM * KT; i += 256) {
            int r = i >> 5, c = i & 31;
            int gr = row0 + r;
            sX[r][c] = (gr < NN) ? X[(size_t)gr * 128 + kt + c] : 0.f;
        }
        __syncthreads();

#pragma unroll 8
        for (int k = 0; k < KT; k++) {
            unsigned long long w2[CPT2];
#pragma unroll
            for (int j = 0; j < CPT2; j++)
                w2[j] = *(const unsigned long long*)&sW[k][tx * CPT2 * 2 + 2 * j];
#pragma unroll
            for (int i = 0; i < RPT; i++) {
                float xv = sX[ty * RPT + i][k];
                unsigned long long xx;
                PACK_DUP_F32(xx, xv);
#pragma unroll
                for (int j = 0; j < CPT2; j++)
                    FMA_F32X2(acc[i][j], xx, w2[j], acc[i][j]);
            }
        }
        __syncthreads();
    }

#pragma unroll
    for (int i = 0; i < RPT; i++) {
        int gr = row0 + ty * RPT + i;
        if (gr < NN) {
#pragma unroll
            for (int j = 0; j < CPT2; j++) {
                float2 f = *reinterpret_cast<float2*>(&acc[i][j]);
                if constexpr (sizeof(OT) == 2) {
                    __half2 h = __float22half2_rn(f);
                    *reinterpret_cast<__half2*>(
                        &Y[(size_t)gr * NC + tx * CPT2 * 2 + 2 * j]) = h;
                } else {
                    *reinterpret_cast<float2*>(
                        &Y[(size_t)gr * NC + tx * CPT2 * 2 + 2 * j]) = f;
                }
            }
        }
    }
}

// ---------------- aggregation: one warp per node ----------------
// hs2 = relu( (sum_e xw_h[src_e]*src_norm[src_e]) * dst_norm + b1 ) * src_norm[node]
// xw rows are fp16: 128 halves = 256B = 8B per lane (4 cols/lane).
__global__ __launch_bounds__(256) void k_agg128(const __half* __restrict__ Y,
                                                const float* __restrict__ bias) {
    int node = (blockIdx.x * blockDim.x + threadIdx.x) >> 5;
    if (node >= NN) return;
    int lane = threadIdx.x & 31;
    int beg = g_row_off[node], end = g_row_off[node + 1];
    float4 acc = make_float4(0.f, 0.f, 0.f, 0.f);
    for (int e = beg; e < end; e++) {
        int s = g_csr_src[e];
        float sn = __ldg(&g_src_norm[s]);              // warp-broadcast
        uint2 raw = __ldg((const uint2*)(Y + (size_t)s * 128) + lane);
        float2 a = __half22float2(*reinterpret_cast<__half2*>(&raw.x));
        float2 b = __half22float2(*reinterpret_cast<__half2*>(&raw.y));
        acc.x = fmaf(a.x, sn, acc.x);
        acc.y = fmaf(a.y, sn, acc.y);
        acc.z = fmaf(b.x, sn, acc.z);
        acc.w = fmaf(b.y, sn, acc.w);
    }
    float dn = g_dst_norm[node];
    float ps = g_src_norm[node];
    float4 b = ((const float4*)bias)[lane];
    float4 o;
    o.x = fmaxf(fmaf(acc.x, dn, b.x), 0.f) * ps;
    o.y = fmaxf(fmaf(acc.y, dn, b.y), 0.f) * ps;
    o.z = fmaxf(fmaf(acc.z, dn, b.z), 0.f) * ps;
    o.w = fmaxf(fmaf(acc.w, dn, b.w), 0.f) * ps;
    ((float4*)(g_hs2 + (size_t)node * 128))[lane] = o;
}

// out = (sum_e hw_h[src_e]) * dst_norm + b2. hw rows fp16: 40 halves = 80B,
// lane<20 handles one half2 (cols 2*lane, 2*lane+1).
__global__ __launch_bounds__(256) void k_agg40(const __half* __restrict__ Y,
                                               const float* __restrict__ bias,
                                               float* __restrict__ out) {
    int node = (blockIdx.x * blockDim.x + threadIdx.x) >> 5;
    if (node >= NN) return;
    int lane = threadIdx.x & 31;
    int beg = g_row_off[node], end = g_row_off[node + 1];
    float2 acc = make_float2(0.f, 0.f);
    if (lane < 20) {
        for (int e = beg; e < end; e++) {
            int s = g_csr_src[e];
            __half2 h = __ldg((const __half2*)(Y + (size_t)s * FC) + lane);
            float2 v = __half22float2(h);
            acc.x += v.x;
            acc.y += v.y;
        }
        float dn = g_dst_norm[node];
        float2 o;
        o.x = fmaf(acc.x, dn, bias[2 * lane]);
        o.y = fmaf(acc.y, dn, bias[2 * lane + 1]);
        *reinterpret_cast<float2*>(out + (size_t)node * FC + 2 * lane) = o;
    }
}

// ---------------- launch ----------------
extern "C" void kernel_launch(void* const* d_in, const int* in_sizes, int n_in,
                              void* d_out, int out_size) {
    const float* x   = (const float*)d_in[0];
    const float* W1  = (const float*)d_in[1];
    const float* b1  = (const float*)d_in[2];
    const float* W2  = (const float*)d_in[3];
    const float* b2  = (const float*)d_in[4];
    const int*   src = (const int*)  d_in[5];
    const int*   dst = (const int*)  d_in[6];
    float* out = (float*)d_out;

    __half *xw, *hw;
    float *hs2;
    cudaGetSymbolAddress((void**)&xw,  g_xw);
    cudaGetSymbolAddress((void**)&hs2, g_hs2);
    cudaGetSymbolAddress((void**)&hw,  g_hw);

    // fork: GEMM1 (independent of graph structure) overlaps the CSR chain
    cudaStream_t s2;
    cudaStreamCreateWithFlags(&s2, cudaStreamNonBlocking);
    cudaEvent_t eFork, eJoin;
    cudaEventCreateWithFlags(&eFork, cudaEventDisableTiming);
    cudaEventCreateWithFlags(&eJoin, cudaEventDisableTiming);

    cudaEventRecord(eFork, 0);
    cudaStreamWaitEvent(s2, eFork, 0);

    k_gemm<128, 16, 4, 8, __half><<<(NN + 127) / 128, 256, 0, s2>>>(x, W1, xw);
    cudaEventRecord(eJoin, s2);

    // main stream: CSR + norms
    k_zero<<<(NN + 255) / 256, 256>>>();
    k_hist<<<(NE + 255) / 256, 256>>>(src, dst);
    k_scanA<<<SCAN_BLKS, 256>>>();
    k_scanB<<<1, 128>>>();
    k_scanC<<<SCAN_BLKS, 256>>>();
    k_fill<<<(NE + 255) / 256, 256>>>(src, dst);

    cudaStreamWaitEvent(0, eJoin, 0);

    k_agg128<<<(NN * 32 + 255) / 256, 256>>>(xw, b1);

    k_gemm<40, 4, 5, 2, __half><<<(NN + 127) / 128, 256>>>(hs2, W2, hw);
    k_agg40<<<(NN * 32 + 255) / 256, 256>>>(hw, b2, out);

    cudaEventDestroy(eFork);
    cudaEventDestroy(eJoin);
    cudaStreamDestroy(s2);
}